// round 11
// baseline (speedup 1.0000x reference)
#include <cuda_runtime.h>
#include <cstdint>

// Lower-triangular matvec: y[i] = sum_{j<=i} W[i,j] * x[j], n = 8192.
//
// R11: column-tile decomposition. Tile = 8 rows x 2048 cols. Block (i,j):
//  - stages x[2048j .. 2048j+2048) into smem ONCE (8 KB),
//  - warp w computes row r = 8i+w over that column slice: 16 float4 __ldcs
//    loads per lane, x from shared memory (LDS) -> global-LDG count is HALVED
//    vs all previous designs and x is off the L1/latency-critical path,
//  - warp partial -> g_part[j][r] (unique writer, no atomics, deterministic).
// Kernel 2 sums the <=4 partials per row into y. Diagonal tiles clip the
// loop to col <= r, so total DRAM traffic is exactly the lower triangle.

#define NT 256
#define TILE_R 8
#define TILE_C 2048
#define TILE_C4 (TILE_C / 4)
#define MAX_N 8192
#define MAX_J (MAX_N / TILE_C)

__device__ float g_part[MAX_J][MAX_N];

__device__ __forceinline__ float dot4(float4 w, float4 v) {
    return w.x * v.x + w.y * v.y + w.z * v.z + w.w * v.w;
}

__global__ __launch_bounds__(NT)
void tril_tile_kernel(const float* __restrict__ x,
                      const float* __restrict__ W,
                      int n)
{
    const int i  = blockIdx.x;            // row tile: rows [8i, 8i+8)
    const int j  = blockIdx.y;            // col tile: cols [2048j, ...)
    const int c0 = j * TILE_C;
    const int r0 = i * TILE_R;

    if (c0 > r0 + TILE_R - 1) return;     // tile wholly above the diagonal

    __shared__ __align__(16) float4 xs[TILE_C4];   // 8 KB x slice

    const int tid = threadIdx.x;
    {
        const float4* __restrict__ xg =
            reinterpret_cast<const float4*>(x) + (c0 >> 2);
        xs[tid]      = __ldg(xg + tid);
        xs[tid + NT] = __ldg(xg + tid + NT);
    }
    __syncthreads();

    const int w    = tid >> 5;
    const int lane = tid & 31;
    const int r    = r0 + w;

    const int cnt = min(r + 1 - c0, TILE_C);   // floats of this row in tile
    if (cnt <= 0) return;                      // row above diagonal slice

    const float4* __restrict__ W4 =
        reinterpret_cast<const float4*>(W + (size_t)r * n + c0);

    float acc;
    if (cnt == TILE_C) {
        // Full tile row: 16 float4 per lane, pure streaming.
        float a0 = 0.f, a1 = 0.f, a2 = 0.f, a3 = 0.f;
        #pragma unroll
        for (int u = 0; u < 16; u += 4) {
            float4 w0 = __ldcs(W4 + lane + 32 * (u + 0));
            float4 w1 = __ldcs(W4 + lane + 32 * (u + 1));
            float4 w2 = __ldcs(W4 + lane + 32 * (u + 2));
            float4 w3 = __ldcs(W4 + lane + 32 * (u + 3));
            a0 += dot4(w0, xs[lane + 32 * (u + 0)]);
            a1 += dot4(w1, xs[lane + 32 * (u + 1)]);
            a2 += dot4(w2, xs[lane + 32 * (u + 2)]);
            a3 += dot4(w3, xs[lane + 32 * (u + 3)]);
        }
        acc = (a0 + a1) + (a2 + a3);
    } else {
        // Diagonal tile row: clipped stream, loads only col <= r.
        const int m4 = cnt >> 2;
        float a0 = 0.f, a1 = 0.f;
        int k = lane;
        for (; k + 32 < m4; k += 64) {
            a0 += dot4(__ldcs(W4 + k),      xs[k]);
            a1 += dot4(__ldcs(W4 + k + 32), xs[k + 32]);
        }
        if (k < m4) a0 += dot4(__ldcs(W4 + k), xs[k]);
        acc = a0 + a1;
        const int tail = cnt & 3;
        if (lane < tail) {
            const int col = c0 + (m4 << 2) + lane;
            acc += W[(size_t)r * n + col] * x[col];
        }
    }

    // Warp reduction; lane 0 writes the unique (j, r) partial.
    #pragma unroll
    for (int off = 16; off > 0; off >>= 1)
        acc += __shfl_down_sync(0xffffffffu, acc, off);
    if (lane == 0)
        g_part[j][r] = acc;
}

__global__ __launch_bounds__(NT)
void reduce_y_kernel(float* __restrict__ y, int n)
{
    const int r = blockIdx.x * NT + threadIdx.x;
    if (r >= n) return;
    const int nj = r / TILE_C;            // highest contributing col tile
    float s = g_part[0][r];
    #pragma unroll
    for (int j = 1; j < MAX_J; j++)
        if (j <= nj) s += g_part[j][r];
    y[r] = s;
}

extern "C" void kernel_launch(void* const* d_in, const int* in_sizes, int n_in,
                              void* d_out, int out_size) {
    const float* x = (const float*)d_in[0];   // [n]
    const float* W = (const float*)d_in[1];   // [n, n] row-major
    float*       y = (float*)d_out;           // [n]

    const int n = in_sizes[0];                // 8192

    dim3 grid(n / TILE_R, n / TILE_C);        // (1024, 4); ~2560 active
    tril_tile_kernel<<<grid, NT>>>(x, W, n);
    reduce_y_kernel<<<(n + NT - 1) / NT, NT>>>(y, n);
}

// round 12
// speedup vs baseline: 1.1221x; 1.1221x over previous
#include <cuda_runtime.h>
#include <cstdint>

// Lower-triangular matvec: y[i] = sum_{j<=i} W[i,j] * x[j]
// n = 8192, W row-major fp32 (lower triangle = 128 MB, streamed once).
//
// R12: loop-free pair-block. Block b covers rows (b, n-1-b): combined
// tot = m0+m1 in {2047,2048} float4s. 512 threads/block, each thread owns
// EXACTLY 4 float4s of the combined index space (j = tid + 512u), so the
// whole kernel is: one 8-LDG batch (4x W __ldcs + 4x x L1-hit) -> 16 FMA ->
// reduce -> exit. No streaming loop => ~4x fewer dynamic instructions than
// R2, so each warp spends nearly all its life with 4 W-float4s in flight
// (vs R2's issue/compute gaps every iteration).

#define NT 512

__device__ __forceinline__ float dot4(float4 w, float4 v) {
    return w.x * v.x + w.y * v.y + w.z * v.z + w.w * v.w;
}

__global__ __launch_bounds__(NT, 2)
void tril_mv_kernel(const float* __restrict__ x,
                    const float* __restrict__ W,
                    float* __restrict__ y,
                    int n)
{
    __shared__ float red0[NT / 32];
    __shared__ float red1[NT / 32];

    const int tid = threadIdx.x;
    const int b   = blockIdx.x;
    const int r0  = b;
    const int r1  = n - 1 - b;

    const int len0 = r0 + 1;
    const int len1 = r1 + 1;            // = n - b
    const int m0   = len0 >> 2;
    const int m1   = len1 >> 2;
    const int tot  = m0 + m1;           // 2047 or 2048

    const float4* __restrict__ W40 =
        reinterpret_cast<const float4*>(W + (size_t)r0 * n);
    const float4* __restrict__ W41 =
        reinterpret_cast<const float4*>(W + (size_t)r1 * n);
    const float4* __restrict__ x4 = reinterpret_cast<const float4*>(x);

    // ---- one batched load phase: 4 W + 4 x loads, all independent ----
    float4 wv[4], xv[4];
    bool   in[4], lo[4];

    #pragma unroll
    for (int u = 0; u < 4; u++) {
        const int j = tid + u * NT;
        in[u] = (j < tot);
        lo[u] = (j < m0);
        const int c = lo[u] ? j : (j - m0);
        const float4* p = lo[u] ? (W40 + j) : (W41 + c);
        if (in[u]) {
            wv[u] = __ldcs(p);
            xv[u] = __ldg(x4 + c);
        }
    }

    // ---- FMA phase ----
    float acc0 = 0.0f, acc1 = 0.0f;
    #pragma unroll
    for (int u = 0; u < 4; u++) {
        if (in[u]) {
            const float p = dot4(wv[u], xv[u]);
            if (lo[u]) acc0 += p; else acc1 += p;
        }
    }

    // ---- scalar tails (<=3 floats per row) ----
    {
        const int t0 = len0 & 3;
        if (tid < t0) {
            const int j = (m0 << 2) + tid;
            acc0 += W[(size_t)r0 * n + j] * x[j];
        }
        const int t1 = len1 & 3;
        if (tid >= 32 && tid < 32 + t1) {
            const int j = (m1 << 2) + (tid - 32);
            acc1 += W[(size_t)r1 * n + j] * x[j];
        }
    }

    // ---- dual block reduction (16 warps) ----
    #pragma unroll
    for (int off = 16; off > 0; off >>= 1) {
        acc0 += __shfl_down_sync(0xffffffffu, acc0, off);
        acc1 += __shfl_down_sync(0xffffffffu, acc1, off);
    }
    const int warp = tid >> 5;
    const int lane = tid & 31;
    if (lane == 0) { red0[warp] = acc0; red1[warp] = acc1; }
    __syncthreads();

    if (warp == 0) {
        float a0 = (lane < NT / 32) ? red0[lane] : 0.0f;
        float a1 = (lane < NT / 32) ? red1[lane] : 0.0f;
        #pragma unroll
        for (int off = (NT / 64); off > 0; off >>= 1) {
            a0 += __shfl_down_sync(0xffffffffu, a0, off);
            a1 += __shfl_down_sync(0xffffffffu, a1, off);
        }
        if (lane == 0) { y[r0] = a0; y[r1] = a1; }
    }
}

extern "C" void kernel_launch(void* const* d_in, const int* in_sizes, int n_in,
                              void* d_out, int out_size) {
    const float* x = (const float*)d_in[0];   // [n]
    const float* W = (const float*)d_in[1];   // [n, n] row-major
    float*       y = (float*)d_out;           // [n]

    const int n = in_sizes[0];                // 8192 (even)

    tril_mv_kernel<<<n / 2, NT>>>(x, W, y, n);
}